// round 3
// baseline (speedup 1.0000x reference)
#include <cuda_runtime.h>
#include <cuda_bf16.h>
#include <cstdint>

// out[r][c] = in[2r+1][2c+1], in: 8192x8192 fp32, out: 4096x4096 fp32.
// Two output rows per block. All 16 input float4 loads front-batched
// (long read burst), then all 8 stores (long write burst) — fewer DRAM
// read/write turnarounds per warp. Streaming cache hints throughout.

#define N_IN   8192
#define N_OUT  4096
#define F4_ROW (N_OUT / 4)   // 1024 output float4s per row
#define TPB    256
#define UNROLL 4             // F4_ROW / TPB
#define ROWS   2             // output rows per block

__global__ __launch_bounds__(TPB) void decimate2_kernel(
    const float4* __restrict__ in, float4* __restrict__ out)
{
    const int orow0 = blockIdx.x * ROWS;
    const int tid   = threadIdx.x;

    float4 a[ROWS][UNROLL], b[ROWS][UNROLL];

    // Front-batched loads: 16 independent LDG.128 in flight per thread.
#pragma unroll
    for (int r = 0; r < ROWS; r++) {
        const float4* in_row = in + (size_t)(2 * (orow0 + r) + 1) * (N_IN / 4);
#pragma unroll
        for (int k = 0; k < UNROLL; k++) {
            const int oc4 = tid + k * TPB;
            a[r][k] = __ldcs(&in_row[2 * oc4]);
            b[r][k] = __ldcs(&in_row[2 * oc4 + 1]);
        }
    }

    // Batched stores: 8 STG.128, contiguous per instruction across the warp.
#pragma unroll
    for (int r = 0; r < ROWS; r++) {
        float4* out_row = out + (size_t)(orow0 + r) * F4_ROW;
#pragma unroll
        for (int k = 0; k < UNROLL; k++) {
            const int oc4 = tid + k * TPB;
            float4 v;
            v.x = a[r][k].y;   // odd col 8*oc4+1
            v.y = a[r][k].w;   // odd col 8*oc4+3
            v.z = b[r][k].y;   // odd col 8*oc4+5
            v.w = b[r][k].w;   // odd col 8*oc4+7
            __stcs(&out_row[oc4], v);
        }
    }
}

extern "C" void kernel_launch(void* const* d_in, const int* in_sizes, int n_in,
                              void* d_out, int out_size)
{
    const float4* in  = (const float4*)d_in[0];
    float4*       out = (float4*)d_out;

    decimate2_kernel<<<N_OUT / ROWS, TPB>>>(in, out);
}